// round 6
// baseline (speedup 1.0000x reference)
#include <cuda_runtime.h>
#include <cstdint>

// ---------------- problem constants ----------------
#define NE   8
#define NT   16384
#define NIN  2048
#define NOUT 2048

// ---------------- GEMM tiling ----------------
#define BM 128
#define BN 256
#define BK 32
#define KITERS (NIN / BK)              // 64
#define STAGES 4
// raw fp32 tiles in smem with 36-float row stride (32 data + 4 pad) ->
// scalar lds.32 fragment gathers are bank-conflict-free.
#define ROWSTRIDE 36
#define A_TILE_FLOATS (BM * ROWSTRIDE) // 4608
#define B_TILE_FLOATS (BN * ROWSTRIDE) // 9216
#define A_TILE_BYTES (A_TILE_FLOATS * 4)   // 18432
#define B_TILE_BYTES (B_TILE_FLOATS * 4)   // 36864
#define STAGE_BYTES (A_TILE_BYTES + B_TILE_BYTES)     // 55296
#define SMEM_CTRL 1024
#define SMEM_TOTAL (SMEM_CTRL + STAGES * STAGE_BYTES) // 222208
#define NTHREADS 320                   // 8 compute warps + 2 producer warps

// ---------------- helpers (all plain-sm_103-legal) ----------------
__device__ __forceinline__ uint32_t smem_u32(const void* p) {
    uint32_t a;
    asm("{ .reg .u64 t; cvta.to.shared.u64 t, %1; cvt.u32.u64 %0, t; }" : "=r"(a) : "l"(p));
    return a;
}

__device__ __forceinline__ uint32_t tf32u(float f) {   // round-to-nearest tf32
    uint32_t r;
    asm("cvt.rna.tf32.f32 %0, %1;" : "=r"(r) : "f"(f));
    return r;
}

__device__ __forceinline__ void cp16(uint32_t smem_dst, const float* gsrc) {
    asm volatile("cp.async.cg.shared.global [%0], [%1], 16;" :: "r"(smem_dst), "l"(gsrc));
}

#define MBAR_INIT(a, c) \
    asm volatile("mbarrier.init.shared.b64 [%0], %1;" :: "r"(a), "r"(c) : "memory")
#define MBAR_ARRIVE(a) \
    asm volatile("mbarrier.arrive.shared.b64 _, [%0];" :: "r"(a) : "memory")
#define CP_MBAR_ARRIVE(a) \
    asm volatile("cp.async.mbarrier.arrive.noinc.shared.b64 [%0];" :: "r"(a) : "memory")

#define MBAR_WAIT(addr, ph) do {                                                   \
    asm volatile("{\n\t.reg .pred P1;\n\t"                                         \
        "WL%=:\n\t"                                                                \
        "mbarrier.try_wait.parity.acquire.cta.shared::cta.b64 P1, [%0], %1, 0x989680;\n\t" \
        "@P1 bra.uni WD%=;\n\t"                                                    \
        "bra.uni WL%=;\n\t"                                                        \
        "WD%=:\n\t}"                                                               \
        :: "r"(addr), "r"(ph) : "memory");                                         \
} while (0)

__device__ __forceinline__ void mma_tf32(float* d, const uint32_t* a, const uint32_t* b) {
    asm volatile(
        "mma.sync.aligned.m16n8k8.row.col.f32.tf32.tf32.f32 "
        "{%0,%1,%2,%3}, {%4,%5,%6,%7}, {%8,%9}, {%0,%1,%2,%3};"
        : "+f"(d[0]), "+f"(d[1]), "+f"(d[2]), "+f"(d[3])
        : "r"(a[0]), "r"(a[1]), "r"(a[2]), "r"(a[3]), "r"(b[0]), "r"(b[1]));
}

// ---------------- fused grouped GEMM: raw-operand warp-specialized pipeline -----
// Producers cp.async raw fp32 x/w tiles (row-major, 36-float smem stride).
// Consumers gather mma fragments with conflict-free lds.32 + cvt.rna.tf32.
__global__ void __launch_bounds__(NTHREADS, 1) gemm_kernel(
        const float* __restrict__ x,
        const float* __restrict__ w,
        const float* __restrict__ bias,
        const int*   __restrict__ tpe,
        float*       __restrict__ out) {
    extern __shared__ __align__(16) char smem[];

    const int e  = blockIdx.z;
    const int mt = blockIdx.y;
    const int nt = blockIdx.x;

    int start = 0, mycnt = 0;
    #pragma unroll
    for (int i = 0; i < NE; i++) {
        int cc = __ldg(tpe + i);
        if (i < e) start += cc;
        if (i == e) mycnt = cc;
    }
    if (mt * BM >= mycnt) return;

    const int tid = threadIdx.x;
    const int m0  = start + mt * BM;            // global token row of tile
    const int nr0 = e * NOUT + nt * BN;         // global w row of tile

    const uint32_t sb     = smem_u32(smem);
    const uint32_t fullb  = sb;                 // STAGES x 8B
    const uint32_t emptyb = sb + 64;            // STAGES x 8B
    const uint32_t dbase  = sb + SMEM_CTRL;

    if (tid == 0) {
        #pragma unroll
        for (int s = 0; s < STAGES; s++) {
            MBAR_INIT(fullb + s * 8, 64);       // 64 producer threads signal
            MBAR_INIT(emptyb + s * 8, 256);     // 256 compute threads signal
        }
    }
    __syncthreads();

    if (tid >= 256) {
        // ================= producer warps (2 warps, 64 threads) =================
        const int ptid = tid - 256;             // 0..63
        const float* xA = x + (size_t)m0 * NIN;
        const float* wB = w + (size_t)nr0 * NIN;
        #pragma unroll 1
        for (int k = 0; k < KITERS; k++) {
            const int s = k & (STAGES - 1);
            if (k >= STAGES) MBAR_WAIT(emptyb + s * 8, ((k >> 2) - 1) & 1);
            const float* As = xA + k * BK;
            const float* Bs = wB + k * BK;
            const uint32_t dA = dbase + s * STAGE_BYTES;
            const uint32_t dB = dA + A_TILE_BYTES;
            #pragma unroll
            for (int i = 0; i < 16; i++) {      // A: 128 rows x 8 chunks of 16B
                int idx = ptid + i * 64;
                int row = idx >> 3, c = idx & 7;
                cp16(dA + row * (ROWSTRIDE * 4) + c * 16,
                     As + (size_t)row * NIN + c * 4);
            }
            #pragma unroll
            for (int i = 0; i < 32; i++) {      // B: 256 rows x 8 chunks of 16B
                int idx = ptid + i * 64;
                int row = idx >> 3, c = idx & 7;
                cp16(dB + row * (ROWSTRIDE * 4) + c * 16,
                     Bs + (size_t)row * NIN + c * 4);
            }
            CP_MBAR_ARRIVE(fullb + s * 8);
        }
    } else {
        // ================= compute warps (8 warps, 256 threads) =================
        const int lane = tid & 31;
        const int wid  = tid >> 5;
        const int wm   = wid & 1;               // 2 warp rows (64 rows each)
        const int wn   = wid >> 1;              // 4 warp cols (64 cols each)
        const int lg   = lane >> 2;             // group id 0..7
        const int lk   = lane & 3;              // k id 0..3

        float acc[4][8][4];
        #pragma unroll
        for (int i = 0; i < 4; i++)
            #pragma unroll
            for (int j = 0; j < 8; j++)
                #pragma unroll
                for (int q = 0; q < 4; q++) acc[i][j][q] = 0.0f;

        #pragma unroll 1
        for (int k = 0; k < KITERS; k++) {
            const int s = k & (STAGES - 1);
            MBAR_WAIT(fullb + s * 8, (k >> 2) & 1);
            const float* sA = (const float*)(smem + SMEM_CTRL + s * STAGE_BYTES);
            const float* sB = sA + A_TILE_FLOATS;
            #pragma unroll
            for (int kcl = 0; kcl < 4; kcl++) {
                const int kc = kcl * 8 + lk;
                uint32_t af[4][4], bf[8][2];
                #pragma unroll
                for (int i = 0; i < 4; i++) {
                    const int r0 = wm * 64 + i * 16 + lg;
                    af[i][0] = tf32u(sA[r0 * ROWSTRIDE + kc]);
                    af[i][1] = tf32u(sA[(r0 + 8) * ROWSTRIDE + kc]);
                    af[i][2] = tf32u(sA[r0 * ROWSTRIDE + kc + 4]);
                    af[i][3] = tf32u(sA[(r0 + 8) * ROWSTRIDE + kc + 4]);
                }
                #pragma unroll
                for (int j = 0; j < 8; j++) {
                    const int n0 = wn * 64 + j * 8 + lg;
                    bf[j][0] = tf32u(sB[n0 * ROWSTRIDE + kc]);
                    bf[j][1] = tf32u(sB[n0 * ROWSTRIDE + kc + 4]);
                }
                #pragma unroll
                for (int i = 0; i < 4; i++)
                    #pragma unroll
                    for (int j = 0; j < 8; j++)
                        mma_tf32(acc[i][j], af[i], bf[j]);
            }
            MBAR_ARRIVE(emptyb + s * 8);        // release: orders prior LDS reads
        }

        // ---- epilogue: bias add + fp32 store ----
        const int ncol0 = nt * BN + wn * 64;
        const float* bptr = bias + (size_t)e * NOUT + ncol0;
        #pragma unroll
        for (int j = 0; j < 8; j++) {
            const int cb = j * 8 + lk * 2;
            const float bx = __ldg(bptr + cb);
            const float by = __ldg(bptr + cb + 1);
            #pragma unroll
            for (int i = 0; i < 4; i++) {
                const int r0 = wm * 64 + i * 16 + lg;
                if (mt * BM + r0 < mycnt) {
                    float2 v = make_float2(acc[i][j][0] + bx, acc[i][j][1] + by);
                    *(float2*)(out + (size_t)(m0 + r0) * NOUT + ncol0 + cb) = v;
                }
                if (mt * BM + r0 + 8 < mycnt) {
                    float2 v = make_float2(acc[i][j][2] + bx, acc[i][j][3] + by);
                    *(float2*)(out + (size_t)(m0 + r0 + 8) * NOUT + ncol0 + cb) = v;
                }
            }
        }
    }
}

// ---------------- host launch ----------------
extern "C" void kernel_launch(void* const* d_in, const int* in_sizes, int n_in,
                              void* d_out, int out_size) {
    const float* x    = (const float*)d_in[0];
    const float* w    = (const float*)d_in[1];
    const float* bias = (const float*)d_in[2];
    const int*   tpe  = (const int*)d_in[3];
    float*       out  = (float*)d_out;

    cudaFuncSetAttribute(gemm_kernel,
                         cudaFuncAttributeMaxDynamicSharedMemorySize, SMEM_TOTAL);
    dim3 grid(NOUT / BN, NT / BM, NE);          // (8, 128, 8), ragged exit
    gemm_kernel<<<grid, NTHREADS, SMEM_TOTAL>>>(x, w, bias, tpe, out);
}